// round 16
// baseline (speedup 1.0000x reference)
#include <cuda_runtime.h>
#include <cuda_fp16.h>
#include <math.h>
#include <stdint.h>

#define Bsz   1024
#define TENC  64
#define SEG   32
#define Hdim  512
#define FOURH 2048
#define BH    (Bsz * Hdim)

#if defined(__CUDA_ARCH__) && (defined(__CUDA_ARCH_FEAT_SM103_ALL) || \
    defined(__CUDA_ARCH_FEAT_SM100_ALL) || defined(__CUDA_ARCH_SPECIFIC__) || \
    defined(__CUDA_ARCH_FAMILY_SPECIFIC__))
#define TC_OK 1
#else
#define TC_OK 0
#endif

// ------------------------- static scratch -------------------------
__device__ __half g_h0[(size_t)97 * BH];
__device__ __half g_h1[(size_t)97 * BH];
__device__ __half g_x[(size_t)65536 * 128];
__device__ __half g_eU0[(size_t)2048 * 512];
__device__ __half g_eU1[(size_t)2048 * 512];
__device__ __half g_dU0[(size_t)2048 * 512];
__device__ __half g_dU1[(size_t)2048 * 512];
__device__ __half g_eW1[(size_t)2048 * 512];
__device__ __half g_dW1[(size_t)2048 * 512];
__device__ __half g_eW0[(size_t)2048 * 128];
__device__ unsigned int g_bar;

struct Params {
    __half *h0, *h1;
    const __half *x;
    const __half *eU0, *eU1, *dU0, *dU1, *eW1, *dW1, *eW0;
    const float *eb0, *eb1, *db0, *db1, *dW0, *dec;
};

// ------------------------- helpers -------------------------
__device__ __forceinline__ uint32_t smem_to_u32(const void* p) {
    uint32_t a;
    asm("{ .reg .u64 t; cvta.to.shared.u64 t, %1; cvt.u32.u64 %0, t; }" : "=r"(a) : "l"(p));
    return a;
}
__device__ __forceinline__ float fast_sig(float x) { return 1.f / (1.f + __expf(-x)); }
__device__ __forceinline__ float fast_tanh(float x) { return 2.f / (1.f + __expf(-2.f * x)) - 1.f; }
__device__ __forceinline__ void lstm_gates(float zi, float zf, float zg, float zo,
                                           float cold, float& cn, float& h) {
    float ig = fast_sig(zi);
    float fg = fast_sig(zf);
    float gg = fast_tanh(zg);
    float og = fast_sig(zo);
    cn = fg * cold + ig * gg;
    h  = og * fast_tanh(cn);
}

#if TC_OK
__device__ __forceinline__ uint32_t elect_one_pred() {
    uint32_t pred;
    asm volatile("{\n\t.reg .pred p;\n\telect.sync _|p, 0xFFFFFFFF;\n\t"
                 "selp.b32 %0, 1, 0, p;\n\t}" : "=r"(pred));
    return pred;
}
#define TCGEN05_ALLOC(addr, n) \
    asm volatile("tcgen05.alloc.cta_group::1.sync.aligned.shared::cta.b32 [%0], %1;" \
                 :: "r"((uint32_t)(addr)), "r"((uint32_t)(n)) : "memory")
#define TCGEN05_DEALLOC(tm, n) \
    asm volatile("tcgen05.dealloc.cta_group::1.sync.aligned.b32 %0, %1;" :: "r"(tm), "r"((uint32_t)(n)))
#define TCGEN05_RELINQ() \
    asm volatile("tcgen05.relinquish_alloc_permit.cta_group::1.sync.aligned;")
#define TCGEN05_COMMIT(mb) \
    asm volatile("tcgen05.commit.cta_group::1.mbarrier::arrive::one.shared::cluster.b64 [%0];" \
                 :: "r"((uint32_t)(mb)) : "memory")
#define TCGEN05_WAIT_LD() asm volatile("tcgen05.wait::ld.sync.aligned;" ::: "memory")
#define TCGEN05_FENCE_AFTER() asm volatile("tcgen05.fence::after_thread_sync;" ::: "memory")
#define MBARRIER_INIT(mb, cnt) \
    asm volatile("mbarrier.init.shared.b64 [%0], %1;" :: "r"((uint32_t)(mb)), "r"((uint32_t)(cnt)) : "memory")
#define FENCE_PROXY_ASYNC() asm volatile("fence.proxy.async.shared::cta;" ::: "memory")
#define CP_ASYNC16(dst, src) \
    asm volatile("cp.async.cg.shared.global [%0], [%1], 16;" :: "r"((uint32_t)(dst)), "l"(src) : "memory")
#define CP_COMMIT() asm volatile("cp.async.commit_group;" ::: "memory")
#define CP_WAIT(n)  asm volatile("cp.async.wait_group %0;" :: "n"(n) : "memory")

#define MBARRIER_WAIT_PARITY(mb, par) do { \
    uint32_t _m = (uint32_t)(mb), _p = (uint32_t)(par), _d; \
    asm volatile("{\n\t.reg .pred p;\n\t" \
        "mbarrier.try_wait.parity.acquire.cta.shared::cta.b64 p, [%1], %2;\n\t" \
        "selp.b32 %0, 1, 0, p;\n\t}" : "=r"(_d) : "r"(_m), "r"(_p) : "memory"); \
    if (!_d) { \
        asm volatile("{\n\t.reg .pred P1;\n\t" \
            "WL_%=:\n\t" \
            "mbarrier.try_wait.parity.acquire.cta.shared::cta.b64 P1, [%0], %1, 0x989680;\n\t" \
            "@P1 bra.uni WD_%=;\n\tbra.uni WL_%=;\n\tWD_%=:\n\t}" \
            :: "r"(_m), "r"(_p) : "memory"); \
    } \
} while (0)

#define TCGEN05_LD_32X32B_X32(r, ta) \
    asm volatile("tcgen05.ld.sync.aligned.32x32b.x32.b32 " \
        "{%0, %1, %2, %3, %4, %5, %6, %7, %8, %9, %10, %11, %12, %13, %14, %15, " \
        " %16, %17, %18, %19, %20, %21, %22, %23, %24, %25, %26, %27, %28, %29, %30, %31}, [%32];" \
        : "=r"((r)[0]), "=r"((r)[1]), "=r"((r)[2]), "=r"((r)[3]), "=r"((r)[4]), "=r"((r)[5]), \
          "=r"((r)[6]), "=r"((r)[7]), "=r"((r)[8]), "=r"((r)[9]), "=r"((r)[10]), "=r"((r)[11]), \
          "=r"((r)[12]), "=r"((r)[13]), "=r"((r)[14]), "=r"((r)[15]), "=r"((r)[16]), "=r"((r)[17]), \
          "=r"((r)[18]), "=r"((r)[19]), "=r"((r)[20]), "=r"((r)[21]), "=r"((r)[22]), "=r"((r)[23]), \
          "=r"((r)[24]), "=r"((r)[25]), "=r"((r)[26]), "=r"((r)[27]), "=r"((r)[28]), "=r"((r)[29]), \
          "=r"((r)[30]), "=r"((r)[31]) : "r"(ta))

static constexpr uint64_t SMEM_DESC_BASE_SW128 =
    (uint64_t(2) << 61) | (uint64_t(1) << 46) | (uint64_t(64) << 32) | (uint64_t(1) << 16);
#define MAKE_SMEM_DESC(a) (SMEM_DESC_BASE_SW128 | ((uint64_t)((a) >> 4) & 0x3FFF))
// kind::f16, fp16 inputs, F32 acc, M=128, N=128
#define MMA_IDESC 0x8200010u

__device__ __forceinline__ void mma_f16_ss(uint32_t d, uint64_t a, uint64_t b, bool acc) {
    uint32_t en = acc ? 1u : 0u;
    asm volatile("{\n\t.reg .pred p;\n\tsetp.ne.u32 p, %5, 0;\n\t"
        "tcgen05.mma.cta_group::1.kind::f16 [%0], %1, %2, %3, {%4, %4, %4, %4}, p;\n\t}"
        :: "r"(d), "l"(a), "l"(b), "r"(MMA_IDESC), "r"(0u), "r"(en) : "memory");
}
#endif // TC_OK

// ------------------- fused conversion (1 launch) -------------------
#define WK (2048 * 512)
__global__ void __launch_bounds__(256) conv_all(
    const float* __restrict__ eU0, const float* __restrict__ eU1,
    const float* __restrict__ dU0, const float* __restrict__ dU1,
    const float* __restrict__ eW1, const float* __restrict__ dW1,
    const float* __restrict__ eW0, const float* __restrict__ x,
    __half* oeU0, __half* oeU1, __half* odU0, __half* odU1,
    __half* oeW1, __half* odW1, __half* oeW0, __half* ox)
{
    size_t idx = (size_t)blockIdx.x * 256 + threadIdx.x;
    const size_t seg6 = (size_t)6 * WK;
    const size_t seg7 = seg6 + 2048 * 128;
    const size_t segE = seg7 + (size_t)65536 * 128;
    if (idx >= segE) return;
    if (idx < seg6) {
        int which = (int)(idx / WK), wk = (int)(idx % WK);
        int n = wk / 512, k = wk % 512;
        int r = n & 127, hT = n >> 7;
        int orig = (r & 3) * 512 + hT * 32 + (r >> 2);
        const float* s = (which == 0) ? eU0 : (which == 1) ? eU1 : (which == 2) ? dU0
                        : (which == 3) ? dU1 : (which == 4) ? eW1 : dW1;
        __half* d = (which == 0) ? oeU0 : (which == 1) ? oeU1 : (which == 2) ? odU0
                   : (which == 3) ? odU1 : (which == 4) ? oeW1 : odW1;
        d[wk] = __float2half(s[(size_t)k * FOURH + orig]);
    } else if (idx < seg7) {
        int wk = (int)(idx - seg6);
        int n = wk / 128, k = wk % 128;
        int r = n & 127, hT = n >> 7;
        int orig = (r & 3) * 512 + hT * 32 + (r >> 2);
        oeW0[wk] = __float2half((k < 121) ? eW0[(size_t)k * FOURH + orig] : 0.f);
    } else {
        size_t wk = idx - seg7;
        int m = (int)(wk >> 7), k = (int)(wk & 127);
        int t = m >> 10, b = m & 1023;
        ox[wk] = __float2half((k < 121) ? x[(size_t)b * (TENC * 121) + t * 121 + k] : 0.f);
    }
}

__global__ void __launch_bounds__(256) zero_init(__half* h0, __half* h1)
{
    int i = blockIdx.x * 256 + threadIdx.x;
    if (i == 0) g_bar = 0;
    if (i >= BH) return;
    __half z = __float2half(0.f);
    h0[i] = z; h1[i] = z;
}

// ------------------- persistent wavefront kernel -------------------
// grid (8, 8, 2) = 128 CTAs, 1/SM, all co-resident. 128 threads.
// 4-stage cp.async pipeline; done barriers re-inited per wave.
#define STAGE_BYTES 49152
#define SMEM_C_OFF  (1024 + 4 * STAGE_BYTES)             // 197632
#define SMEM_BYTES  (SMEM_C_OFF + 128 * 65 * 4)           // 230912

__global__ void __launch_bounds__(128) lstm_persist(Params P)
{
    extern __shared__ char smem[];
    const uint32_t sb = smem_to_u32(smem);
    const uint32_t tb = (sb + 1023u) & ~1023u;
    char* smemc = smem + (tb - sb);

    const int tid = threadIdx.x;
    const int nb = blockIdx.x;
    const int z  = (int)blockIdx.z;
    const size_t rowBase = (size_t)blockIdx.y * 128;
    const size_t colBase = (size_t)nb * 256;

    float* scf = (float*)(smemc + SMEM_C_OFF); // [128][65] persistent c tile
    for (int i = tid; i < 128 * 65; i += 128) scf[i] = 0.f;

#if TC_OK
    if (tid < 32) { TCGEN05_ALLOC(tb, 256); TCGEN05_RELINQ(); }
    // done barriers: tb+24,32,40,48 (buf 0..3); MBF: tb+56
    if (tid == 0) {
        MBARRIER_INIT(tb + 24, 1);
        MBARRIER_INIT(tb + 32, 1);
        MBARRIER_INIT(tb + 40, 1);
        MBARRIER_INIT(tb + 48, 1);
        MBARRIER_INIT(tb + 56, 1);
    }
    __syncthreads();
    uint32_t tmem;
    asm volatile("ld.shared.b32 %0, [%1];" : "=r"(tmem) : "r"(tb));
#else
    __syncthreads();
#endif

    for (int w = 0; w <= 96; w++) {
        const bool active = (z == 0) ? (w < 96) : (w >= 1);
        if (active) {
            const int t = (z == 0) ? w : (w - 1);
            const __half *A1, *B1;
            const __half *A2 = nullptr, *B2 = nullptr;
            const float *bias, *dec = nullptr, *dW0p = nullptr;
            __half *oh;
            int kA2 = 0;
            if (z == 0) {
                A1 = P.h0 + (size_t)t * BH;
                oh = P.h0 + (size_t)(t + 1) * BH;
                if (t < TENC) {
                    B1 = P.eU0;
                    A2 = P.x + (size_t)t * 1024 * 128;
                    B2 = P.eW0; kA2 = 128;
                    bias = P.eb0;
                } else {
                    B1 = P.dU0;
                    bias = P.db0; dec = P.dec + (t - TENC); dW0p = P.dW0;
                }
            } else {
                A1 = P.h1 + (size_t)t * BH;
                oh = P.h1 + (size_t)(t + 1) * BH;
                A2 = P.h0 + (size_t)(t + 1) * BH;
                kA2 = 512;
                if (t < TENC) { B1 = P.eU1; B2 = P.eW1; bias = P.eb1; }
                else          { B1 = P.dU1; B2 = P.dW1; bias = P.db1; }
            }
            const int kA1 = 512;
            const int ch1 = 8;
            const int nch = ch1 + (kA2 >> 6);

#if TC_OK
#define LOAD_CHUNK(cc) do { \
        const uint32_t _st = tb + 1024 + (uint32_t)((cc) & 3) * STAGE_BYTES; \
        const __half *_A, *_B; int _kA, _ko; \
        if ((cc) < ch1) { _A = A1; _B = B1; _kA = kA1; _ko = (cc) * 64; } \
        else { _A = A2; _B = B2; _kA = kA2; _ko = ((cc) - ch1) * 64; } \
        _Pragma("unroll") \
        for (int _i = 0; _i < 8; _i++) { \
            int _a = _i * 128 + tid; \
            int _r = _a >> 3, _s = _a & 7; \
            uint32_t _off = (uint32_t)(_r * 128 + _s * 16); \
            _off ^= (_off >> 3) & 0x70; \
            CP_ASYNC16(_st + _off, _A + (rowBase + _r) * (size_t)_kA + _ko + _s * 8); \
        } \
        _Pragma("unroll") \
        for (int _i = 0; _i < 16; _i++) { \
            int _a = _i * 128 + tid; \
            int _r = _a >> 3, _s = _a & 7; \
            uint32_t _off = (uint32_t)(_r * 128 + _s * 16); \
            _off ^= (_off >> 3) & 0x70; \
            CP_ASYNC16(_st + 16384 + _off, _B + (colBase + _r) * (size_t)_kA + _ko + _s * 8); \
        } \
        CP_COMMIT(); \
    } while (0)

            // prologue: 3 chunks (buffers 0,1,2); buffer 3 filled at iter 0
            LOAD_CHUNK(0);
            LOAD_CHUNK(1);
            LOAD_CHUNK(2);

            for (int c = 0; c < nch; c++) {
                // head: load chunk c+3 (buffer (c+3)&3 == (c-1)&3, chunk c-1's MMA)
                if (c + 3 < nch) {
                    if (c >= 1)
                        MBARRIER_WAIT_PARITY(tb + 24 + (uint32_t)((c - 1) & 3) * 8,
                                             ((c - 1) >> 2) & 1);
                    LOAD_CHUNK(c + 3);
                }
                // ensure chunk c's cp.async group landed
                int hi = (c + 3 < nch) ? (c + 3) : (nch - 1);
                int pend = hi - c;
                if (pend >= 3)      CP_WAIT(3);
                else if (pend == 2) CP_WAIT(2);
                else if (pend == 1) CP_WAIT(1);
                else                CP_WAIT(0);
                __syncthreads();
                if (tid < 32 && elect_one_pred()) {
                    const uint32_t st = tb + 1024 + (uint32_t)(c & 3) * STAGE_BYTES;
                    uint64_t ad = MAKE_SMEM_DESC(st);
                    uint64_t bd = MAKE_SMEM_DESC(st + 16384);
#pragma unroll
                    for (int j = 0; j < 4; j++) {
                        bool acc = !(c == 0 && j == 0);
                        mma_f16_ss(tmem,       ad + j * 2, bd + j * 2,        acc);
                        mma_f16_ss(tmem + 128, ad + j * 2, bd + 1024 + j * 2, acc);
                    }
                    TCGEN05_COMMIT(tb + 24 + (uint32_t)(c & 3) * 8);
                }
            }
#undef LOAD_CHUNK

            if (tid < 32 && elect_one_pred()) TCGEN05_COMMIT(tb + 56);
            __syncthreads();
            MBARRIER_WAIT_PARITY(tb + 56, 0);
            TCGEN05_FENCE_AFTER();
            __syncthreads();
            // re-init barriers for next wave (all commits completed, all waits returned)
            if (tid == 0) {
                MBARRIER_INIT(tb + 24, 1);
                MBARRIER_INIT(tb + 32, 1);
                MBARRIER_INIT(tb + 40, 1);
                MBARRIER_INIT(tb + 48, 1);
                MBARRIER_INIT(tb + 56, 1);
            }

            // ---- epilogue: c stays in SMEM; h staged then coalesced writeback ----
            __half* shi = (__half*)(smemc + 1024);           // [128][66]
            const size_t row = rowBase + tid;
            const float dv = dec ? dec[row * SEG] : 0.f;

            for (int q = 0; q < 8; q++) {
                uint32_t dr[32];
                TCGEN05_LD_32X32B_X32(dr, tmem + q * 32);
                TCGEN05_WAIT_LD();
                const int nlb = ((q & 4) ? 32 : 0) + (q & 3) * 8;
#pragma unroll
                for (int jj = 0; jj < 8; jj++) {
                    int nl = nlb + jj;
                    int hg = nb * 64 + nl;
                    float zi = __uint_as_float(dr[jj * 4 + 0]) + bias[hg];
                    float zf = __uint_as_float(dr[jj * 4 + 1]) + bias[512 + hg];
                    float zg = __uint_as_float(dr[jj * 4 + 2]) + bias[1024 + hg];
                    float zo = __uint_as_float(dr[jj * 4 + 3]) + bias[1536 + hg];
                    if (dec) {
                        zi += dv * dW0p[hg];
                        zf += dv * dW0p[512 + hg];
                        zg += dv * dW0p[1024 + hg];
                        zo += dv * dW0p[1536 + hg];
                    }
                    float cn2, h;
                    lstm_gates(zi, zf, zg, zo, scf[tid * 65 + nl], cn2, h);
                    scf[tid * 65 + nl] = cn2;
                    shi[tid * 66 + nl] = __float2half(h);
                }
            }
            __syncthreads();
#pragma unroll 4
            for (int i = 0; i < 64; i++) {
                int idx = i * 128 + tid, r = idx >> 6, cc = idx & 63;
                oh[(rowBase + r) * Hdim + nb * 64 + cc] = shi[r * 66 + cc];
            }
#else
            // ---------- FFMA fallback (non-'a' pass; unused when 'a' cubin loads) ----------
            float* sA = (float*)(smemc + 1024);                // [32][132]
            float* sB = (float*)(smemc + 1024 + 16896);        // [32][68]
            const int tr = tid >> 3, tc8 = tid & 7;
            for (int pass = 0; pass < 4; pass++) {
                float acc[8][8];
#pragma unroll
                for (int r = 0; r < 8; r++)
#pragma unroll
                    for (int j = 0; j < 8; j++) acc[r][j] = 0.f;
                for (int part = 0; part < 2; part++) {
                    if (part == 1 && !A2) break;
                    const __half* Ap = part ? A2 : A1;
                    const __half* Bp = part ? B2 : B1;
                    const int kA = part ? kA2 : kA1;
                    for (int k0 = 0; k0 < kA; k0 += 32) {
                        __syncthreads();
#pragma unroll 4
                        for (int i = 0; i < 32; i++) {
                            int idx = i * 128 + tid, r = idx >> 5, kk = idx & 31;
                            sA[kk * 132 + r] = __half2float(Ap[(rowBase + r) * (size_t)kA + k0 + kk]);
                        }
#pragma unroll 2
                        for (int i = 0; i < 16; i++) {
                            int idx = i * 128 + tid, r = idx >> 5, kk = idx & 31;
                            sB[kk * 68 + r] = __half2float(Bp[(colBase + pass * 64 + r) * (size_t)kA + k0 + kk]);
                        }
                        __syncthreads();
#pragma unroll
                        for (int k = 0; k < 32; k++) {
                            float a[8], b[8];
#pragma unroll
                            for (int r = 0; r < 8; r++) a[r] = sA[k * 132 + tr * 8 + r];
#pragma unroll
                            for (int j = 0; j < 8; j++) b[j] = sB[k * 68 + tc8 * 8 + j];
#pragma unroll
                            for (int r = 0; r < 8; r++)
#pragma unroll
                                for (int j = 0; j < 8; j++) acc[r][j] += a[r] * b[j];
                        }
                    }
                }
                __syncthreads();
#pragma unroll
                for (int r = 0; r < 8; r++) {
                    int lr = tr * 8 + r;
                    size_t row = rowBase + lr;
                    float dvr = dec ? dec[row * SEG] : 0.f;
#pragma unroll
                    for (int q = 0; q < 2; q++) {
                        int nl = ((pass & 2) ? 32 : 0) + (pass & 1) * 16 + tc8 * 2 + q;
                        int hg = nb * 64 + nl;
                        float zi = acc[r][q * 4 + 0] + bias[hg];
                        float zf = acc[r][q * 4 + 1] + bias[512 + hg];
                        float zg = acc[r][q * 4 + 2] + bias[1024 + hg];
                        float zo = acc[r][q * 4 + 3] + bias[1536 + hg];
                        if (dec) {
                            zi += dvr * dW0p[hg];
                            zf += dvr * dW0p[512 + hg];
                            zg += dvr * dW0p[1024 + hg];
                            zo += dvr * dW0p[1536 + hg];
                        }
                        float cn2, h;
                        lstm_gates(zi, zf, zg, zo, scf[lr * 65 + nl], cn2, h);
                        scf[lr * 65 + nl] = cn2;
                        oh[row * Hdim + hg] = __float2half(h);
                    }
                }
                __syncthreads();
            }
#endif
        }

        // -------- grid-wide wave barrier (all 128 CTAs co-resident) --------
        __threadfence();
        __syncthreads();
        if (tid == 0) {
            atomicAdd(&g_bar, 1u);
            unsigned tgt = 128u * (unsigned)(w + 1), v;
            do {
                asm volatile("ld.acquire.gpu.u32 %0, [%1];" : "=r"(v) : "l"(&g_bar) : "memory");
            } while (v < tgt);
        }
        __syncthreads();
    }

#if TC_OK
    if (tid < 32) TCGEN05_DEALLOC(tmem, 256);
#endif
}

// ------------------- final dense -------------------
__global__ void __launch_bounds__(256) dense_kernel(
    const __half* __restrict__ hh, const float* __restrict__ W,
    const float* __restrict__ bb, float* __restrict__ out)
{
    int wid = (blockIdx.x * blockDim.x + threadIdx.x) >> 5;
    int lane = threadIdx.x & 31;
    if (wid >= Bsz * SEG) return;
    int b = wid / SEG, s = wid % SEG;
    size_t base = (size_t)(TENC + 1 + s) * BH + (size_t)b * Hdim;
    float sum = 0.f;
#pragma unroll 4
    for (int k = lane; k < Hdim; k += 32)
        sum += __half2float(hh[base + k]) * W[k];
#pragma unroll
    for (int o = 16; o > 0; o >>= 1) sum += __shfl_down_sync(0xffffffffu, sum, o);
    if (lane == 0) out[(size_t)b * SEG + s] = sum + bb[0];
}

// ------------------- host -------------------
extern "C" void kernel_launch(void* const* d_in, const int* in_sizes, int n_in,
                              void* d_out, int out_size)
{
    const float* x      = (const float*)d_in[0];
    const float* decin  = (const float*)d_in[1];
    const float* eW0    = (const float*)d_in[2];
    const float* eU0    = (const float*)d_in[3];
    const float* eb0    = (const float*)d_in[4];
    const float* eW1    = (const float*)d_in[5];
    const float* eU1    = (const float*)d_in[6];
    const float* eb1    = (const float*)d_in[7];
    const float* dW0    = (const float*)d_in[8];
    const float* dU0    = (const float*)d_in[9];
    const float* db0    = (const float*)d_in[10];
    const float* dW1    = (const float*)d_in[11];
    const float* dU1    = (const float*)d_in[12];
    const float* db1    = (const float*)d_in[13];
    const float* denseW = (const float*)d_in[14];
    const float* denseb = (const float*)d_in[15];
    float* out = (float*)d_out;

    cudaFuncSetAttribute(lstm_persist, cudaFuncAttributeMaxDynamicSharedMemorySize, SMEM_BYTES);

    Params P;
    cudaGetSymbolAddress((void**)&P.h0, g_h0);
    cudaGetSymbolAddress((void**)&P.h1, g_h1);
    cudaGetSymbolAddress((void**)&P.x, g_x);
    cudaGetSymbolAddress((void**)&P.eU0, g_eU0);
    cudaGetSymbolAddress((void**)&P.eU1, g_eU1);
    cudaGetSymbolAddress((void**)&P.dU0, g_dU0);
    cudaGetSymbolAddress((void**)&P.dU1, g_dU1);
    cudaGetSymbolAddress((void**)&P.eW1, g_eW1);
    cudaGetSymbolAddress((void**)&P.dW1, g_dW1);
    cudaGetSymbolAddress((void**)&P.eW0, g_eW0);
    P.eb0 = eb0; P.eb1 = eb1; P.db0 = db0; P.db1 = db1; P.dW0 = dW0; P.dec = decin;

    {
        size_t total = (size_t)6 * WK + 2048 * 128 + (size_t)65536 * 128;
        conv_all<<<(int)((total + 255) / 256), 256>>>(
            eU0, eU1, dU0, dU1, eW1, dW1, eW0, x,
            (__half*)P.eU0, (__half*)P.eU1, (__half*)P.dU0, (__half*)P.dU1,
            (__half*)P.eW1, (__half*)P.dW1, (__half*)P.eW0, (__half*)P.x);
    }
    zero_init<<<(BH + 255) / 256, 256>>>(P.h0, P.h1);

    lstm_persist<<<dim3(8, 8, 2), 128, SMEM_BYTES>>>(P);

    dense_kernel<<<(Bsz * SEG * 32) / 256, 256>>>(P.h1, denseW, denseb, out);
}